// round 5
// baseline (speedup 1.0000x reference)
#include <cuda_runtime.h>
#include <math.h>

#define BB   32
#define TT   512
#define HH   256
#define CC   32
#define G4   1024   // 4*H
#define DD   256

// ---------------- scratch (no allocations allowed) ----------------
__device__ float g_gx[(size_t)2 * TT * G4 * BB];     // [dir][t][col][b]   134 MB
__device__ float g_hist[(size_t)2 * TT * HH * BB];   // [dir][t][n][b]      33 MB
__device__ float g_logits[(size_t)TT * BB * CC];     // [t][b][c]            2 MB
__device__ int   g_ctr[2 * TT];                      // per-direction, per-step barrier counters

// ---------------- init: zero barrier counters each replay ----------------
__global__ void init_kernel() {
    int i = blockIdx.x * blockDim.x + threadIdx.x;
    if (i < 2 * TT) g_ctr[i] = 0;
}

// ---------------- kernel A: embedding gather + x@Wi + bias ----------------
// grid (512, 16): x = t, y = dir*8 + colblock(128 cols). 256 threads.
// smem: a_sm [256][33] (padded) + w_sm [64][128]
__global__ void wi_gemm_kernel(const int* __restrict__ chars,
                               const int* __restrict__ bigrams,
                               const float* __restrict__ char_table,
                               const float* __restrict__ bigram_table,
                               const float* __restrict__ Wi_f,
                               const float* __restrict__ bias_f,
                               const float* __restrict__ Wi_b,
                               const float* __restrict__ bias_b) {
    extern __shared__ float sm[];
    float* a_sm = sm;              // 256*33 = 8448 floats
    float* w_sm = sm + 8448;       // 64*128 = 8192 floats

    const int t   = blockIdx.x;
    const int yid = blockIdx.y;
    const int dir = yid >> 3;
    const int cb  = yid & 7;
    const float* Wi   = dir ? Wi_b  : Wi_f;
    const float* bias = dir ? bias_b : bias_f;

    const int tid  = threadIdx.x;
    const int lane = tid & 31;
    const int wp   = tid >> 5;

    // gather A tile: emb[b][0..255] -> a_sm[k][b]
    for (int q = 0; q < 4; q++) {
        int b  = wp * 4 + q;
        int ci = chars[b * TT + t];
        int bi = bigrams[b * TT + t];
        #pragma unroll
        for (int h2 = 0; h2 < 2; h2++) {
            int k4 = lane + h2 * 32;   // float4 index 0..63
            float4 v;
            if (k4 < 32) v = ((const float4*)char_table)[(size_t)ci * 32 + k4];
            else         v = ((const float4*)bigram_table)[(size_t)bi * 32 + (k4 - 32)];
            int k = k4 * 4;
            a_sm[(k + 0) * 33 + b] = v.x;
            a_sm[(k + 1) * 33 + b] = v.y;
            a_sm[(k + 2) * 33 + b] = v.z;
            a_sm[(k + 3) * 33 + b] = v.w;
        }
    }

    const int bb = tid & 31;
    const int cg = tid >> 5;       // 8 groups of 16 cols
    float acc[16];
    #pragma unroll
    for (int j = 0; j < 16; j++) acc[j] = 0.f;

    for (int ch = 0; ch < 4; ch++) {
        __syncthreads();
        int k0 = ch * 64;
        // load W chunk [64][128]
        #pragma unroll
        for (int it = 0; it < 8; it++) {
            int idx = tid + it * 256;       // 0..2047 float4
            int kk  = idx >> 5;
            int c4  = idx & 31;
            float4 wv = ((const float4*)(Wi + (size_t)(k0 + kk) * G4 + cb * 128))[c4];
            *((float4*)&w_sm[kk * 128 + c4 * 4]) = wv;
        }
        __syncthreads();
        #pragma unroll 8
        for (int kk = 0; kk < 64; kk++) {
            float av = a_sm[(k0 + kk) * 33 + bb];
            const float4* wr = (const float4*)&w_sm[kk * 128 + cg * 16];
            float4 w0 = wr[0], w1 = wr[1], w2 = wr[2], w3 = wr[3];
            acc[0]  += av * w0.x; acc[1]  += av * w0.y; acc[2]  += av * w0.z; acc[3]  += av * w0.w;
            acc[4]  += av * w1.x; acc[5]  += av * w1.y; acc[6]  += av * w1.z; acc[7]  += av * w1.w;
            acc[8]  += av * w2.x; acc[9]  += av * w2.y; acc[10] += av * w2.z; acc[11] += av * w2.w;
            acc[12] += av * w3.x; acc[13] += av * w3.y; acc[14] += av * w3.z; acc[15] += av * w3.w;
        }
    }

    float* outp = g_gx + (size_t)(dir * TT + t) * G4 * BB;
    #pragma unroll
    for (int j = 0; j < 16; j++) {
        int col = cb * 128 + cg * 16 + j;
        outp[(size_t)col * BB + bb] = acc[j] + bias[col];
    }
}

// ---------------- kernel B: recurrent scan (both directions) ----------------
__device__ __forceinline__ float sigf(float x) { return 1.f / (1.f + expf(-x)); }

// grid 128 CTAs (<=148 SMs -> all co-resident), 128 threads each.
// CTA (dir, s): owns h columns [4s, 4s+4), gate cols {g*256 + 4s + nn}.
__global__ void __launch_bounds__(128) scan_kernel(const float* __restrict__ Wh_f,
                                                   const float* __restrict__ Wh_b,
                                                   const int* __restrict__ seq_len) {
    extern __shared__ float sm[];
    float* sm_wh = sm;                 // [256][16] = 4096 floats
    float* sm_h  = sm + 4096;          // [256][32] = 8192 floats
    float* sm_g  = sm + 4096 + 8192;   // [4][4][32] = 512 floats

    const int cta = blockIdx.x;
    const int dir = cta >> 6;
    const int s   = cta & 63;
    const float* Wh = dir ? Wh_b : Wh_f;

    const int tid = threadIdx.x;
    const int b   = tid & 31;
    const int w   = tid >> 5;          // warp id: gate in GEMM phase, nn in combine phase

    // load Wh slice once: sm_wh[k*16 + gate*4 + nn]
    for (int idx = tid; idx < 4096; idx += 128) {
        int k  = idx >> 4;
        int jj = idx & 15;
        sm_wh[idx] = Wh[(size_t)k * G4 + (jj >> 2) * 256 + s * 4 + (jj & 3)];
    }

    const int sl = seq_len[b];
    const int n_glob = s * 4 + w;
    float c_reg = 0.f;

    for (int p = 0; p < TT; p++) {
        const int t = dir ? (TT - 1 - p) : p;

        // stage previous h into smem
        if (p == 0) {
            for (int i = tid; i < HH * BB; i += 128) sm_h[i] = 0.f;
        } else {
            int tp = dir ? (t + 1) : (t - 1);
            const float4* src = (const float4*)(g_hist + (size_t)(dir * TT + tp) * HH * BB);
            float4* dst = (float4*)sm_h;
            #pragma unroll
            for (int i = 0; i < 16; i++) dst[tid + i * 128] = src[tid + i * 128];
        }
        __syncthreads();

        // gates = gx + h @ Wh (thread: batch b, gate w, 4 n's)
        const float* gxp = g_gx + (size_t)(dir * TT + t) * G4 * BB;
        const int col0 = w * 256 + s * 4;
        float a0 = gxp[(size_t)(col0 + 0) * BB + b];
        float a1 = gxp[(size_t)(col0 + 1) * BB + b];
        float a2 = gxp[(size_t)(col0 + 2) * BB + b];
        float a3 = gxp[(size_t)(col0 + 3) * BB + b];
        const float4* wh4 = (const float4*)sm_wh;
        #pragma unroll 16
        for (int k = 0; k < 256; k++) {
            float  hv = sm_h[k * 32 + b];
            float4 ww = wh4[k * 4 + w];
            a0 += hv * ww.x; a1 += hv * ww.y; a2 += hv * ww.z; a3 += hv * ww.w;
        }
        sm_g[w * 128 + 0 * 32 + b] = a0;
        sm_g[w * 128 + 1 * 32 + b] = a1;
        sm_g[w * 128 + 2 * 32 + b] = a2;
        sm_g[w * 128 + 3 * 32 + b] = a3;
        __syncthreads();

        // combine (thread: batch b, n = s*4 + w)
        float gi = sm_g[0 * 128 + w * 32 + b];
        float gf = sm_g[1 * 128 + w * 32 + b];
        float gg = sm_g[2 * 128 + w * 32 + b];
        float go = sm_g[3 * 128 + w * 32 + b];
        float c_new = sigf(gf) * c_reg + sigf(gi) * tanhf(gg);
        float h_new = sigf(go) * tanhf(c_new);
        bool  m = (t < sl);
        if (m) c_reg = c_new;
        float h_prev = sm_h[n_glob * 32 + b];
        float h_out  = m ? h_new : h_prev;
        g_hist[((size_t)(dir * TT + t) * HH + n_glob) * BB + b] = h_out;

        // inter-CTA barrier (per direction), skip after last step
        if (p < TT - 1) {
            __threadfence();
            __syncthreads();
            if (tid == 0) {
                atomicAdd(&g_ctr[dir * TT + p], 1);
                volatile int* vp = &g_ctr[dir * TT + p];
                while (*vp < 64) { }
                __threadfence();
            }
            __syncthreads();
        }
    }
}

// ---------------- kernel C: output projection + log_softmax ----------------
// grid 512 (t), 256 threads. smem: hsm[512][32] + wsm[512][32] + lsm[32][33] + lse[32]
__global__ void proj_kernel(const float* __restrict__ out_W,
                            const float* __restrict__ out_b) {
    extern __shared__ float sm[];
    float* hsm = sm;                       // 512*32
    float* wsm = sm + 512 * 32;            // 512*32
    float* lsm = wsm + 512 * 32;           // 32*33
    float* lse = lsm + 32 * 33;            // 32

    const int t   = blockIdx.x;
    const int tid = threadIdx.x;

    float4* hd = (float4*)hsm;
    const float4* h0 = (const float4*)(g_hist + (size_t)t * HH * BB);
    const float4* h1 = (const float4*)(g_hist + (size_t)(TT + t) * HH * BB);
    #pragma unroll
    for (int i = 0; i < 16; i++) {
        int idx = tid + i * 256;           // 0..4095 float4
        hd[idx] = (idx < 2048) ? h0[idx] : h1[idx - 2048];
    }
    float4* wd = (float4*)wsm;
    const float4* w4 = (const float4*)out_W;
    #pragma unroll
    for (int i = 0; i < 16; i++) {
        int idx = tid + i * 256;
        wd[idx] = w4[idx];
    }
    __syncthreads();

    const int b  = tid & 31;
    const int cg = tid >> 5;               // 8 groups of 4 classes
    float acc[4];
    #pragma unroll
    for (int j = 0; j < 4; j++) acc[j] = out_b[cg * 4 + j];
    #pragma unroll 8
    for (int k = 0; k < 512; k++) {
        float  hv = hsm[k * 32 + b];
        float4 ww = *(const float4*)&wsm[k * 32 + cg * 4];
        acc[0] += hv * ww.x; acc[1] += hv * ww.y; acc[2] += hv * ww.z; acc[3] += hv * ww.w;
    }
    #pragma unroll
    for (int j = 0; j < 4; j++) lsm[b * 33 + cg * 4 + j] = acc[j];
    __syncthreads();

    if (tid < 32) {
        float mx = -1e30f;
        #pragma unroll
        for (int c = 0; c < 32; c++) mx = fmaxf(mx, lsm[tid * 33 + c]);
        float ssum = 0.f;
        #pragma unroll
        for (int c = 0; c < 32; c++) ssum += expf(lsm[tid * 33 + c] - mx);
        lse[tid] = mx + logf(ssum);
    }
    __syncthreads();

    float l = lse[b];
    #pragma unroll
    for (int j = 0; j < 4; j++)
        g_logits[(size_t)t * BB * CC + b * CC + cg * 4 + j] = acc[j] - l;
}

// ---------------- kernel D: CRF normalizer + gold score ----------------
// grid 32 (b), 32 threads (lane = state j)
__global__ void crf_kernel(const int* __restrict__ seq_len,
                           const int* __restrict__ target,
                           const float* __restrict__ trans,
                           const float* __restrict__ start_trans,
                           const float* __restrict__ end_trans,
                           float* __restrict__ out) {
    const int b = blockIdx.x;
    const int j = threadIdx.x;
    const int sl = seq_len[b];

    float tr[32];
    #pragma unroll
    for (int i = 0; i < 32; i++) tr[i] = trans[i * 32 + j];

    float alpha = g_logits[(size_t)b * CC + j] + start_trans[j];

    for (int t = 1; t < sl; t++) {
        float emit = g_logits[(size_t)t * BB * CC + b * CC + j];
        float mx = -1e30f;
        #pragma unroll
        for (int i = 0; i < 32; i++) {
            float ai = __shfl_sync(0xffffffffu, alpha, i);
            mx = fmaxf(mx, ai + tr[i]);
        }
        float ssum = 0.f;
        #pragma unroll
        for (int i = 0; i < 32; i++) {
            float ai = __shfl_sync(0xffffffffu, alpha, i);
            ssum += __expf(ai + tr[i] - mx);
        }
        alpha = mx + logf(ssum) + emit;
    }

    // normalizer = LSE_j(alpha + end_trans)
    float v  = alpha + end_trans[j];
    float mx = v;
    #pragma unroll
    for (int o = 16; o > 0; o >>= 1) mx = fmaxf(mx, __shfl_xor_sync(0xffffffffu, mx, o));
    float se = __expf(v - mx);
    #pragma unroll
    for (int o = 16; o > 0; o >>= 1) se += __shfl_xor_sync(0xffffffffu, se, o);
    float norm = mx + logf(se);

    // gold path score (lanes strided over t)
    float gs = 0.f;
    for (int t = j; t < sl; t += 32) {
        int tg = target[b * TT + t];
        gs += g_logits[(size_t)t * BB * CC + b * CC + tg];
        if (t >= 1) gs += trans[target[b * TT + t - 1] * 32 + tg];
    }
    #pragma unroll
    for (int o = 16; o > 0; o >>= 1) gs += __shfl_xor_sync(0xffffffffu, gs, o);

    if (j == 0) {
        gs += start_trans[target[b * TT]] + end_trans[target[b * TT + sl - 1]];
        out[b] = norm - gs;
    }
}

// ---------------- launch ----------------
extern "C" void kernel_launch(void* const* d_in, const int* in_sizes, int n_in,
                              void* d_out, int out_size) {
    const int*   chars        = (const int*)d_in[0];
    const int*   bigrams      = (const int*)d_in[1];
    const int*   seq_len      = (const int*)d_in[2];
    const int*   target       = (const int*)d_in[3];
    const float* char_table   = (const float*)d_in[4];
    const float* bigram_table = (const float*)d_in[5];
    const float* Wi_f         = (const float*)d_in[6];
    const float* Wh_f         = (const float*)d_in[7];
    const float* b_f          = (const float*)d_in[8];
    const float* Wi_b         = (const float*)d_in[9];
    const float* Wh_b         = (const float*)d_in[10];
    const float* b_b          = (const float*)d_in[11];
    const float* out_W        = (const float*)d_in[12];
    const float* out_b        = (const float*)d_in[13];
    const float* trans        = (const float*)d_in[14];
    const float* start_trans  = (const float*)d_in[15];
    const float* end_trans    = (const float*)d_in[16];
    float* out = (float*)d_out;

    const int SMEM_A = (256 * 33 + 64 * 128) * (int)sizeof(float);          // 66560
    const int SMEM_S = (4096 + 8192 + 512) * (int)sizeof(float);            // 51200
    const int SMEM_P = (512 * 32 * 2 + 32 * 33 + 32) * (int)sizeof(float);  // 135424

    cudaFuncSetAttribute(wi_gemm_kernel, cudaFuncAttributeMaxDynamicSharedMemorySize, SMEM_A);
    cudaFuncSetAttribute(scan_kernel,    cudaFuncAttributeMaxDynamicSharedMemorySize, SMEM_S);
    cudaFuncSetAttribute(proj_kernel,    cudaFuncAttributeMaxDynamicSharedMemorySize, SMEM_P);

    init_kernel<<<4, 256>>>();

    dim3 ga(TT, 16);
    wi_gemm_kernel<<<ga, 256, SMEM_A>>>(chars, bigrams, char_table, bigram_table,
                                        Wi_f, b_f, Wi_b, b_b);

    scan_kernel<<<128, 128, SMEM_S>>>(Wh_f, Wh_b, seq_len);

    proj_kernel<<<TT, 256, SMEM_P>>>(out_W, out_b);

    crf_kernel<<<BB, 32>>>(seq_len, target, trans, start_trans, end_trans, out);
}

// round 6
// speedup vs baseline: 1.1340x; 1.1340x over previous
#include <cuda_runtime.h>
#include <math.h>

#define BB   32
#define TT   512
#define HH   256
#define CC   32
#define G4   1024   // 4*H
#define DD   256

typedef unsigned long long ull;

// ---------------- scratch (no allocations allowed) ----------------
__device__ float g_gx[(size_t)2 * TT * G4 * BB];     // [dir][t][col][b]   134 MB
__device__ float g_hist[(size_t)2 * TT * HH * BB];   // [dir][t][n][b]      33 MB
__device__ float g_logits[(size_t)TT * BB * CC];     // [t][b][c]            2 MB
__device__ int   g_ctr[2 * TT];                      // per-direction, per-step barrier counters

// ---------------- packed fp32x2 helpers ----------------
__device__ __forceinline__ ull ffma2(ull a, ull b, ull c) {
    ull d;
    asm("fma.rn.f32x2 %0, %1, %2, %3;" : "=l"(d) : "l"(a), "l"(b), "l"(c));
    return d;
}
__device__ __forceinline__ ull padd2(ull a, ull b) {
    ull d;
    asm("add.rn.f32x2 %0, %1, %2;" : "=l"(d) : "l"(a), "l"(b));
    return d;
}
__device__ __forceinline__ ull dup2(float x) {
    ull p = (ull)__float_as_uint(x);
    return p | (p << 32);
}

__device__ __forceinline__ float sigf(float x)  { return __fdividef(1.f, 1.f + __expf(-x)); }
__device__ __forceinline__ float tanhf_(float x){ return __fdividef(2.f, 1.f + __expf(-2.f * x)) - 1.f; }

// ---------------- init: zero barrier counters each replay ----------------
__global__ void init_kernel() {
    int i = blockIdx.x * blockDim.x + threadIdx.x;
    if (i < 2 * TT) g_ctr[i] = 0;
}

// ---------------- kernel A: embedding gather + x@Wi + bias (fp32x2) ----------------
// grid (512, 16): x = t, y = dir*8 + colblock(128 cols). 256 threads.
// smem: a_sm [256][32] floats (32KB) + wd_sm [64][128] ull duplicated (64KB)
__global__ void __launch_bounds__(256) wi_gemm_kernel(
        const int* __restrict__ chars,
        const int* __restrict__ bigrams,
        const float* __restrict__ char_table,
        const float* __restrict__ bigram_table,
        const float* __restrict__ Wi_f,
        const float* __restrict__ bias_f,
        const float* __restrict__ Wi_b,
        const float* __restrict__ bias_b) {
    extern __shared__ float sm[];
    float* a_sm = sm;                       // 8192 floats = 32KB
    ull*   wd_sm = (ull*)(sm + 8192);       // 8192 ull = 64KB

    const int t   = blockIdx.x;
    const int yid = blockIdx.y;
    const int dir = yid >> 3;
    const int cb  = yid & 7;
    const float* Wi   = dir ? Wi_b  : Wi_f;
    const float* bias = dir ? bias_b : bias_f;

    const int tid = threadIdx.x;

    // ---- gather emb -> a_sm[k][b]  (lane = b -> conflict-free STS) ----
    {
        const int b    = tid & 31;
        const int part = tid >> 5;   // 0..7, each handles 8 float4 of the 64-float4 row
        const int ci = chars[b * TT + t];
        const int bi = bigrams[b * TT + t];
        #pragma unroll
        for (int i = 0; i < 8; i++) {
            int k4 = part * 8 + i;   // 0..63
            float4 v;
            if (k4 < 32) v = ((const float4*)char_table)[(size_t)ci * 32 + k4];
            else         v = ((const float4*)bigram_table)[(size_t)bi * 32 + (k4 - 32)];
            a_sm[(k4 * 4 + 0) * 32 + b] = v.x;
            a_sm[(k4 * 4 + 1) * 32 + b] = v.y;
            a_sm[(k4 * 4 + 2) * 32 + b] = v.z;
            a_sm[(k4 * 4 + 3) * 32 + b] = v.w;
        }
    }

    // ---- GEMM mapping: thread = (4 cols, 4 batches) ----
    const int cg = tid >> 3;   // 0..31 : cols cg*4 .. cg*4+3
    const int bq = tid & 7;    // batches 4bq .. 4bq+3
    ull acc[8];
    #pragma unroll
    for (int i = 0; i < 8; i++) acc[i] = 0ull;

    const ulonglong2* a2 = (const ulonglong2*)a_sm;

    for (int ch = 0; ch < 4; ch++) {
        const int k0 = ch * 64;
        __syncthreads();
        // load Wi chunk duplicated: wd_sm[kk*128 + col] = {w,w}
        // consecutive-lane scalar stores -> conflict-free
        for (int u = tid; u < 8192; u += 256) {
            int kk  = u >> 7;
            int col = u & 127;
            float wv = Wi[(size_t)(k0 + kk) * G4 + cb * 128 + col];
            wd_sm[u] = dup2(wv);
        }
        __syncthreads();
        #pragma unroll 8
        for (int kk = 0; kk < 64; kk++) {
            ulonglong2 hv = a2[(k0 + kk) * 8 + bq];   // 4 batches: (b0,b1),(b2,b3)
            const ull* wr = &wd_sm[kk * 128 + cg * 4];
            #pragma unroll
            for (int c = 0; c < 4; c++) {
                ull wd = wr[c];
                acc[2 * c]     = ffma2(hv.x, wd, acc[2 * c]);
                acc[2 * c + 1] = ffma2(hv.y, wd, acc[2 * c + 1]);
            }
        }
    }

    float* outp = g_gx + (size_t)(dir * TT + t) * G4 * BB;
    #pragma unroll
    for (int c = 0; c < 4; c++) {
        int col = cb * 128 + cg * 4 + c;
        ull b2 = dup2(bias[col]);
        ulonglong2 r;
        r.x = padd2(acc[2 * c], b2);
        r.y = padd2(acc[2 * c + 1], b2);
        *(ulonglong2*)(outp + (size_t)col * BB + bq * 4) = r;
    }
}

// ---------------- kernel B: recurrent scan (both directions, fp32x2) ----------------
// grid 128 CTAs, 128 threads. CTA (dir, s): owns h columns [4s,4s+4) -> 16 gate cols.
// smem: whd [256][16] ull dup (32KB) | h [256][32] f32 (32KB) | g [16][32] f32 (2KB)
__global__ void __launch_bounds__(128, 1) scan_kernel(const float* __restrict__ Wh_f,
                                                      const float* __restrict__ Wh_b,
                                                      const int* __restrict__ seq_len) {
    extern __shared__ float sm[];
    ull*   sm_whd = (ull*)sm;              // 4096 ull
    float* sm_h   = sm + 8192;             // 8192 floats
    float* sm_g   = sm + 8192 + 8192;      // 512 floats

    const int cta = blockIdx.x;
    const int dir = cta >> 6;
    const int s   = cta & 63;
    const float* Wh = dir ? Wh_b : Wh_f;

    const int tid = threadIdx.x;
    // GEMM mapping
    const int j  = tid >> 3;   // local gate-col 0..15  (g = j>>2, nn = j&3)
    const int bq = tid & 7;    // batch quad
    // combine mapping
    const int b = tid & 31;
    const int w = tid >> 5;    // nn

    // load duplicated Wh slice: whd[k*16 + j] = {w,w}, consecutive-lane stores
    for (int idx = tid; idx < 4096; idx += 128) {
        int k  = idx >> 4;
        int jj = idx & 15;
        float wv = Wh[(size_t)k * G4 + (jj >> 2) * 256 + s * 4 + (jj & 3)];
        sm_whd[idx] = dup2(wv);
    }

    const int sl     = seq_len[b];
    const int n_glob = s * 4 + w;
    const int gcol   = (j >> 2) * 256 + s * 4 + (j & 3);
    float c_reg = 0.f;

    // prefetch gx for first step
    const int t_first = dir ? (TT - 1) : 0;
    ulonglong2 gx_pre =
        *(const ulonglong2*)(g_gx + ((size_t)(dir * TT + t_first) * G4 + gcol) * BB + bq * 4);

    const ulonglong2* h2 = (const ulonglong2*)sm_h;

    for (int p = 0; p < TT; p++) {
        const int t = dir ? (TT - 1 - p) : p;

        // stage previous h into smem
        if (p == 0) {
            float4* dst = (float4*)sm_h;
            #pragma unroll
            for (int i = 0; i < 16; i++) dst[tid + i * 128] = make_float4(0.f, 0.f, 0.f, 0.f);
        } else {
            const int tp = dir ? (t + 1) : (t - 1);
            const float4* src = (const float4*)(g_hist + (size_t)(dir * TT + tp) * HH * BB);
            float4* dst = (float4*)sm_h;
            #pragma unroll
            for (int i = 0; i < 16; i++) dst[tid + i * 128] = src[tid + i * 128];
        }
        __syncthreads();

        // gates = gx + h @ Wh   (packed: 2 FFMA2 per k)
        ull a01 = gx_pre.x;
        ull a23 = gx_pre.y;
        #pragma unroll 8
        for (int k = 0; k < 256; k++) {
            ulonglong2 hv = h2[k * 8 + bq];
            ull wd = sm_whd[k * 16 + j];
            a01 = ffma2(hv.x, wd, a01);
            a23 = ffma2(hv.y, wd, a23);
        }
        {
            ulonglong2 r; r.x = a01; r.y = a23;
            *(ulonglong2*)&sm_g[j * 32 + bq * 4] = r;
        }
        __syncthreads();

        // combine (thread: batch b, n = s*4 + w)
        float gi = sm_g[(0 + w)  * 32 + b];
        float gf = sm_g[(4 + w)  * 32 + b];
        float gg = sm_g[(8 + w)  * 32 + b];
        float go = sm_g[(12 + w) * 32 + b];
        float c_new = sigf(gf) * c_reg + sigf(gi) * tanhf_(gg);
        float h_new = sigf(go) * tanhf_(c_new);
        bool  m = (t < sl);
        if (m) c_reg = c_new;
        float h_prev = sm_h[n_glob * 32 + b];
        float h_out  = m ? h_new : h_prev;
        g_hist[((size_t)(dir * TT + t) * HH + n_glob) * BB + b] = h_out;

        if (p < TT - 1) {
            __threadfence();
            // prefetch next step's gx: latency hidden by the barrier
            const int t_next = dir ? (t - 1) : (t + 1);
            gx_pre = *(const ulonglong2*)(g_gx +
                        ((size_t)(dir * TT + t_next) * G4 + gcol) * BB + bq * 4);
            __syncthreads();
            if (tid == 0) {
                atomicAdd(&g_ctr[dir * TT + p], 1);
                volatile int* vp = &g_ctr[dir * TT + p];
                while (*vp < 64) { }
                __threadfence();
            }
            __syncthreads();
        }
    }
}

// ---------------- kernel C: output projection + log_softmax ----------------
__global__ void proj_kernel(const float* __restrict__ out_W,
                            const float* __restrict__ out_b) {
    extern __shared__ float sm[];
    float* hsm = sm;                       // 512*32
    float* wsm = sm + 512 * 32;            // 512*32
    float* lsm = wsm + 512 * 32;           // 32*33
    float* lse = lsm + 32 * 33;            // 32

    const int t   = blockIdx.x;
    const int tid = threadIdx.x;

    float4* hd = (float4*)hsm;
    const float4* h0 = (const float4*)(g_hist + (size_t)t * HH * BB);
    const float4* h1 = (const float4*)(g_hist + (size_t)(TT + t) * HH * BB);
    #pragma unroll
    for (int i = 0; i < 16; i++) {
        int idx = tid + i * 256;
        hd[idx] = (idx < 2048) ? h0[idx] : h1[idx - 2048];
    }
    float4* wd = (float4*)wsm;
    const float4* w4 = (const float4*)out_W;
    #pragma unroll
    for (int i = 0; i < 16; i++) {
        int idx = tid + i * 256;
        wd[idx] = w4[idx];
    }
    __syncthreads();

    const int b  = tid & 31;
    const int cg = tid >> 5;
    float acc[4];
    #pragma unroll
    for (int jj = 0; jj < 4; jj++) acc[jj] = out_b[cg * 4 + jj];
    #pragma unroll 8
    for (int k = 0; k < 512; k++) {
        float  hv = hsm[k * 32 + b];
        float4 ww = *(const float4*)&wsm[k * 32 + cg * 4];
        acc[0] += hv * ww.x; acc[1] += hv * ww.y; acc[2] += hv * ww.z; acc[3] += hv * ww.w;
    }
    #pragma unroll
    for (int jj = 0; jj < 4; jj++) lsm[b * 33 + cg * 4 + jj] = acc[jj];
    __syncthreads();

    if (tid < 32) {
        float mx = -1e30f;
        #pragma unroll
        for (int c = 0; c < 32; c++) mx = fmaxf(mx, lsm[tid * 33 + c]);
        float ssum = 0.f;
        #pragma unroll
        for (int c = 0; c < 32; c++) ssum += expf(lsm[tid * 33 + c] - mx);
        lse[tid] = mx + logf(ssum);
    }
    __syncthreads();

    float l = lse[b];
    #pragma unroll
    for (int jj = 0; jj < 4; jj++)
        g_logits[(size_t)t * BB * CC + b * CC + cg * 4 + jj] = acc[jj] - l;
}

// ---------------- kernel D: CRF normalizer + gold score ----------------
__global__ void crf_kernel(const int* __restrict__ seq_len,
                           const int* __restrict__ target,
                           const float* __restrict__ trans,
                           const float* __restrict__ start_trans,
                           const float* __restrict__ end_trans,
                           float* __restrict__ out) {
    const int b = blockIdx.x;
    const int j = threadIdx.x;
    const int sl = seq_len[b];

    float tr[32];
    #pragma unroll
    for (int i = 0; i < 32; i++) tr[i] = trans[i * 32 + j];

    float alpha = g_logits[(size_t)b * CC + j] + start_trans[j];

    for (int t = 1; t < sl; t++) {
        float emit = g_logits[(size_t)t * BB * CC + b * CC + j];
        float mx = -1e30f;
        #pragma unroll
        for (int i = 0; i < 32; i++) {
            float ai = __shfl_sync(0xffffffffu, alpha, i);
            mx = fmaxf(mx, ai + tr[i]);
        }
        float ssum = 0.f;
        #pragma unroll
        for (int i = 0; i < 32; i++) {
            float ai = __shfl_sync(0xffffffffu, alpha, i);
            ssum += __expf(ai + tr[i] - mx);
        }
        alpha = mx + __logf(ssum) + emit;
    }

    float v  = alpha + end_trans[j];
    float mx = v;
    #pragma unroll
    for (int o = 16; o > 0; o >>= 1) mx = fmaxf(mx, __shfl_xor_sync(0xffffffffu, mx, o));
    float se = __expf(v - mx);
    #pragma unroll
    for (int o = 16; o > 0; o >>= 1) se += __shfl_xor_sync(0xffffffffu, se, o);
    float norm = mx + logf(se);

    float gs = 0.f;
    for (int t = j; t < sl; t += 32) {
        int tg = target[b * TT + t];
        gs += g_logits[(size_t)t * BB * CC + b * CC + tg];
        if (t >= 1) gs += trans[target[b * TT + t - 1] * 32 + tg];
    }
    #pragma unroll
    for (int o = 16; o > 0; o >>= 1) gs += __shfl_xor_sync(0xffffffffu, gs, o);

    if (j == 0) {
        gs += start_trans[target[b * TT]] + end_trans[target[b * TT + sl - 1]];
        out[b] = norm - gs;
    }
}

// ---------------- launch ----------------
extern "C" void kernel_launch(void* const* d_in, const int* in_sizes, int n_in,
                              void* d_out, int out_size) {
    const int*   chars        = (const int*)d_in[0];
    const int*   bigrams      = (const int*)d_in[1];
    const int*   seq_len      = (const int*)d_in[2];
    const int*   target       = (const int*)d_in[3];
    const float* char_table   = (const float*)d_in[4];
    const float* bigram_table = (const float*)d_in[5];
    const float* Wi_f         = (const float*)d_in[6];
    const float* Wh_f         = (const float*)d_in[7];
    const float* b_f          = (const float*)d_in[8];
    const float* Wi_b         = (const float*)d_in[9];
    const float* Wh_b         = (const float*)d_in[10];
    const float* b_b          = (const float*)d_in[11];
    const float* out_W        = (const float*)d_in[12];
    const float* out_b        = (const float*)d_in[13];
    const float* trans        = (const float*)d_in[14];
    const float* start_trans  = (const float*)d_in[15];
    const float* end_trans    = (const float*)d_in[16];
    float* out = (float*)d_out;

    const int SMEM_A = 32768 + 65536;                                       // 98304
    const int SMEM_S = 32768 + 32768 + 2048;                                // 67584
    const int SMEM_P = (512 * 32 * 2 + 32 * 33 + 32) * (int)sizeof(float);  // 135424

    cudaFuncSetAttribute(wi_gemm_kernel, cudaFuncAttributeMaxDynamicSharedMemorySize, SMEM_A);
    cudaFuncSetAttribute(scan_kernel,    cudaFuncAttributeMaxDynamicSharedMemorySize, SMEM_S);
    cudaFuncSetAttribute(proj_kernel,    cudaFuncAttributeMaxDynamicSharedMemorySize, SMEM_P);

    init_kernel<<<4, 256>>>();

    dim3 ga(TT, 16);
    wi_gemm_kernel<<<ga, 256, SMEM_A>>>(chars, bigrams, char_table, bigram_table,
                                        Wi_f, b_f, Wi_b, b_b);

    scan_kernel<<<128, 128, SMEM_S>>>(Wh_f, Wh_b, seq_len);

    proj_kernel<<<TT, 256, SMEM_P>>>(out_W, out_b);

    crf_kernel<<<BB, 32>>>(seq_len, target, trans, start_trans, end_trans, out);
}